// round 1
// baseline (speedup 1.0000x reference)
#include <cuda_runtime.h>
#include <math_constants.h>

// Problem constants
#define BB 16
#define TT 2048
#define CC 384
#define DD 64

// Scratch for q, k, v projections: [B*T, 64] each (8 MB each)
__device__ float g_q[BB * TT * DD];
__device__ float g_k[BB * TT * DD];
__device__ float g_v[BB * TT * DD];

// ---------------------------------------------------------------------------
// Kernel 1: fused QKV projection. grid = (512 row-tiles, 3 matrices).
// Each block: 64 rows x 64 cols, K tiled by 32. 256 threads, 4x4 micro-tile.
// ---------------------------------------------------------------------------
__global__ __launch_bounds__(256) void proj_kernel(
    const float* __restrict__ x,
    const float* __restrict__ Wq,
    const float* __restrict__ Wk,
    const float* __restrict__ Wv)
{
    __shared__ float xs[64][36];   // 64 rows x 32 cols (+4 pad)
    __shared__ float ws[32][68];   // 32 rows x 64 cols (+4 pad)

    const float* W;
    float* out;
    if (blockIdx.y == 0)      { W = Wq; out = g_q; }
    else if (blockIdx.y == 1) { W = Wk; out = g_k; }
    else                      { W = Wv; out = g_v; }

    const int tid = threadIdx.x;
    const int ti = tid >> 4, tj = tid & 15;
    const int r0 = ti * 4, c0 = tj * 4;
    const int rowBase = blockIdx.x * 64;

    float acc[4][4];
#pragma unroll
    for (int i = 0; i < 4; i++)
#pragma unroll
        for (int j = 0; j < 4; j++) acc[i][j] = 0.0f;

    const int xr = tid >> 2;
    const int xc = (tid & 3) * 4;
    const int wr = tid >> 3;
    const int wc = (tid & 7) * 4;

    for (int kk = 0; kk < CC; kk += 32) {
        // Load x tile: 64 x 32
        float4 v0 = *(const float4*)&x[(rowBase + xr) * CC + kk + xc];
        float4 v1 = *(const float4*)&x[(rowBase + xr) * CC + kk + xc + 16];
        *(float4*)&xs[xr][xc]      = v0;
        *(float4*)&xs[xr][xc + 16] = v1;
        // Load W tile: 32 x 64
        *(float4*)&ws[wr][wc]      = *(const float4*)&W[(kk + wr) * DD + wc];
        *(float4*)&ws[wr][wc + 32] = *(const float4*)&W[(kk + wr) * DD + wc + 32];
        __syncthreads();

#pragma unroll
        for (int k = 0; k < 32; k++) {
            float a0 = xs[r0 + 0][k];
            float a1 = xs[r0 + 1][k];
            float a2 = xs[r0 + 2][k];
            float a3 = xs[r0 + 3][k];
            float4 bb = *(float4*)&ws[k][c0];
            acc[0][0] += a0 * bb.x; acc[0][1] += a0 * bb.y; acc[0][2] += a0 * bb.z; acc[0][3] += a0 * bb.w;
            acc[1][0] += a1 * bb.x; acc[1][1] += a1 * bb.y; acc[1][2] += a1 * bb.z; acc[1][3] += a1 * bb.w;
            acc[2][0] += a2 * bb.x; acc[2][1] += a2 * bb.y; acc[2][2] += a2 * bb.z; acc[2][3] += a2 * bb.w;
            acc[3][0] += a3 * bb.x; acc[3][1] += a3 * bb.y; acc[3][2] += a3 * bb.z; acc[3][3] += a3 * bb.w;
        }
        __syncthreads();
    }

#pragma unroll
    for (int ii = 0; ii < 4; ii++) {
        float4 o = make_float4(acc[ii][0], acc[ii][1], acc[ii][2], acc[ii][3]);
        *(float4*)&out[(rowBase + r0 + ii) * DD + c0] = o;
    }
}

// ---------------------------------------------------------------------------
// Kernel 2: flash attention, fp32. One block per (b, 64-row q tile).
// Online softmax. Replicates reference quirk: causal-masked OR exactly-zero
// scaled score -> -inf.
// smem: qs[64][68], kst[64][68] (K transposed: [d][s]), vs[64][68], ps[64][68]
// ---------------------------------------------------------------------------
#define SMSTRIDE 68
#define TILE_F (64 * SMSTRIDE)

__global__ __launch_bounds__(256) void attn_kernel(float* __restrict__ out)
{
    extern __shared__ float sm[];
    float* qs  = sm;
    float* kst = sm + TILE_F;
    float* vs  = sm + 2 * TILE_F;
    float* ps  = sm + 3 * TILE_F;

    const int b  = blockIdx.y;
    const int qt = (gridDim.x - 1) - blockIdx.x;  // longest tiles first
    const int tid = threadIdx.x;
    const int ti = tid >> 4, tj = tid & 15;
    const int r0 = ti * 4, c0 = tj * 4;
    const int rowg = b * TT + qt * 64;

    const float NEG_INF = -CUDART_INF_F;

    // Load q tile, prescale by 1/sqrt(64) = 0.125 (exact power of two)
    {
        const int r = tid >> 2;
        const int cb = (tid & 3) * 4;
#pragma unroll
        for (int u = 0; u < 4; u++) {
            float4 v = *(const float4*)&g_q[(rowg + r) * DD + cb + u * 16];
            v.x *= 0.125f; v.y *= 0.125f; v.z *= 0.125f; v.w *= 0.125f;
            *(float4*)&qs[r * SMSTRIDE + cb + u * 16] = v;
        }
    }

    float o[4][4];
#pragma unroll
    for (int i = 0; i < 4; i++)
#pragma unroll
        for (int j = 0; j < 4; j++) o[i][j] = 0.0f;
    float m[4] = {NEG_INF, NEG_INF, NEG_INF, NEG_INF};
    float l[4] = {0.0f, 0.0f, 0.0f, 0.0f};

    for (int st = 0; st <= qt; st++) {
        __syncthreads();  // previous P@V done before overwriting kst/vs/ps
        // Load K (transposed into kst[d][s]) and V tiles
        {
            const int s = tid >> 2;
            const int db = (tid & 3) * 4;
            const int srow = (b * TT + st * 64 + s) * DD;
#pragma unroll
            for (int u = 0; u < 4; u++) {
                const int d = db + u * 16;
                float4 kv = *(const float4*)&g_k[srow + d];
                kst[(d + 0) * SMSTRIDE + s] = kv.x;
                kst[(d + 1) * SMSTRIDE + s] = kv.y;
                kst[(d + 2) * SMSTRIDE + s] = kv.z;
                kst[(d + 3) * SMSTRIDE + s] = kv.w;
                float4 vv = *(const float4*)&g_v[srow + d];
                *(float4*)&vs[s * SMSTRIDE + d] = vv;
            }
        }
        __syncthreads();

        // S = (q*scale) @ K^T   (64x64, 4x4 per thread)
        float sacc[4][4];
#pragma unroll
        for (int i = 0; i < 4; i++)
#pragma unroll
            for (int j = 0; j < 4; j++) sacc[i][j] = 0.0f;
#pragma unroll 16
        for (int d = 0; d < 64; d++) {
            float a0 = qs[(r0 + 0) * SMSTRIDE + d];
            float a1 = qs[(r0 + 1) * SMSTRIDE + d];
            float a2 = qs[(r0 + 2) * SMSTRIDE + d];
            float a3 = qs[(r0 + 3) * SMSTRIDE + d];
            float4 bb = *(float4*)&kst[d * SMSTRIDE + c0];
            sacc[0][0] += a0 * bb.x; sacc[0][1] += a0 * bb.y; sacc[0][2] += a0 * bb.z; sacc[0][3] += a0 * bb.w;
            sacc[1][0] += a1 * bb.x; sacc[1][1] += a1 * bb.y; sacc[1][2] += a1 * bb.z; sacc[1][3] += a1 * bb.w;
            sacc[2][0] += a2 * bb.x; sacc[2][1] += a2 * bb.y; sacc[2][2] += a2 * bb.z; sacc[2][3] += a2 * bb.w;
            sacc[3][0] += a3 * bb.x; sacc[3][1] += a3 * bb.y; sacc[3][2] += a3 * bb.z; sacc[3][3] += a3 * bb.w;
        }

        // Mask: upper-triangular (diag tile) OR exactly-zero -> -inf
        const bool diag = (st == qt);
#pragma unroll
        for (int ii = 0; ii < 4; ii++)
#pragma unroll
            for (int jj = 0; jj < 4; jj++) {
                float v = sacc[ii][jj];
                if ((diag && (c0 + jj) > (r0 + ii)) || v == 0.0f) v = NEG_INF;
                sacc[ii][jj] = v;
            }

        // Online softmax update (per-row, reduce across the 16 tj lanes)
#pragma unroll
        for (int ii = 0; ii < 4; ii++) {
            float rm = fmaxf(fmaxf(sacc[ii][0], sacc[ii][1]),
                             fmaxf(sacc[ii][2], sacc[ii][3]));
#pragma unroll
            for (int msk = 1; msk < 16; msk <<= 1)
                rm = fmaxf(rm, __shfl_xor_sync(0xffffffffu, rm, msk));
            const float mn = fmaxf(m[ii], rm);
            const float fac = (m[ii] == NEG_INF) ? 0.0f : __expf(m[ii] - mn);
            float p0 = (sacc[ii][0] == NEG_INF) ? 0.0f : __expf(sacc[ii][0] - mn);
            float p1 = (sacc[ii][1] == NEG_INF) ? 0.0f : __expf(sacc[ii][1] - mn);
            float p2 = (sacc[ii][2] == NEG_INF) ? 0.0f : __expf(sacc[ii][2] - mn);
            float p3 = (sacc[ii][3] == NEG_INF) ? 0.0f : __expf(sacc[ii][3] - mn);
            float psum = p0 + p1 + p2 + p3;
#pragma unroll
            for (int msk = 1; msk < 16; msk <<= 1)
                psum += __shfl_xor_sync(0xffffffffu, psum, msk);
            l[ii] = l[ii] * fac + psum;
            m[ii] = mn;
            o[ii][0] *= fac; o[ii][1] *= fac; o[ii][2] *= fac; o[ii][3] *= fac;
            *(float4*)&ps[(r0 + ii) * SMSTRIDE + c0] = make_float4(p0, p1, p2, p3);
        }
        __syncthreads();

        // O += P @ V
#pragma unroll 16
        for (int s = 0; s < 64; s++) {
            float a0 = ps[(r0 + 0) * SMSTRIDE + s];
            float a1 = ps[(r0 + 1) * SMSTRIDE + s];
            float a2 = ps[(r0 + 2) * SMSTRIDE + s];
            float a3 = ps[(r0 + 3) * SMSTRIDE + s];
            float4 bb = *(float4*)&vs[s * SMSTRIDE + c0];
            o[0][0] += a0 * bb.x; o[0][1] += a0 * bb.y; o[0][2] += a0 * bb.z; o[0][3] += a0 * bb.w;
            o[1][0] += a1 * bb.x; o[1][1] += a1 * bb.y; o[1][2] += a1 * bb.z; o[1][3] += a1 * bb.w;
            o[2][0] += a2 * bb.x; o[2][1] += a2 * bb.y; o[2][2] += a2 * bb.z; o[2][3] += a2 * bb.w;
            o[3][0] += a3 * bb.x; o[3][1] += a3 * bb.y; o[3][2] += a3 * bb.z; o[3][3] += a3 * bb.w;
        }
    }

    // Epilogue: normalize and store
#pragma unroll
    for (int ii = 0; ii < 4; ii++) {
        const float inv = 1.0f / l[ii];
        float4 res = make_float4(o[ii][0] * inv, o[ii][1] * inv,
                                 o[ii][2] * inv, o[ii][3] * inv);
        *(float4*)&out[(rowg + r0 + ii) * DD + c0] = res;
    }
}

// ---------------------------------------------------------------------------
extern "C" void kernel_launch(void* const* d_in, const int* in_sizes, int n_in,
                              void* d_out, int out_size)
{
    (void)in_sizes; (void)n_in; (void)out_size;
    const float* x  = (const float*)d_in[0];
    const float* Wq = (const float*)d_in[1];
    const float* Wk = (const float*)d_in[2];
    const float* Wv = (const float*)d_in[3];
    float* out = (float*)d_out;

    const int smem_bytes = 4 * TILE_F * (int)sizeof(float);  // 69632
    cudaFuncSetAttribute(attn_kernel,
                         cudaFuncAttributeMaxDynamicSharedMemorySize, smem_bytes);

    proj_kernel<<<dim3(BB * TT / 64, 3), 256>>>(x, Wq, Wk, Wv);
    attn_kernel<<<dim3(TT / 64, BB), 256, smem_bytes>>>(out);
}